// round 8
// baseline (speedup 1.0000x reference)
#include <cuda_runtime.h>

#define NF    32
#define NDOF  29
#define BLK   128           // 64 batches per block, 2 threads per batch (rows 01 / 23)
#define BSTR  68            // slab floats per batch (17 float4, bank-staggered)

__device__ __forceinline__ void fast_sincos(float a, float &s, float &c) {
    float q  = rintf(a * 0.63661977236758134f);
    int   iq = (int)q;
    float r  = fmaf(q, -1.5707962513e+0f, a);
    r        = fmaf(q, -7.5497894159e-8f, r);
    float r2 = r * r;
    float ps = fmaf(r2, -1.9841270e-4f, 8.3333333e-3f);
    ps       = fmaf(r2, ps, -1.6666667e-1f);
    float sr = fmaf(r * r2, ps, r);
    float pc = fmaf(r2, -1.3888889e-3f, 4.1666668e-2f);
    pc       = fmaf(r2, pc, -5.0e-1f);
    float cr = fmaf(r2, pc, 1.0f);
    bool  sw = (iq & 1);
    float ss = sw ? cr : sr;
    float cc = sw ? sr : cr;
    unsigned sgn_s = ((unsigned)(iq & 2)) << 30;
    unsigned sgn_c = ((unsigned)((iq + 1) & 2)) << 30;
    s = __uint_as_float(__float_as_uint(ss) ^ sgn_s);
    c = __uint_as_float(__float_as_uint(cc) ^ sgn_c);
}

__global__ void __launch_bounds__(BLK, 7)
fk_kernel(const float* __restrict__ ja,        // [B, 29]
          const float* __restrict__ axes,      // [32, 3]
          const float* __restrict__ origins,   // [32, 4, 4]
          const float* __restrict__ mmult,     // [2]
          const float* __restrict__ moff,      // [2]
          const int*   __restrict__ ctrl,      // [29]
          const int*   __restrict__ msrc,      // [2]
          const int*   __restrict__ mdst,      // [2]
          const int*   __restrict__ types,     // [32]
          float*       __restrict__ out,       // [B, 32, 4, 4]
          int Bn)
{
    // Per (frame, row j in 0..2) constants, 3 x float4:
    //   cA = (O_j.xyz, O_j.w)
    //   cB = (O_j x k [revolute], O_j.k [prismatic])
    //   cC = ((O_j.k)k - O_j.xyz [revolute], 0)
    // L_j.xyz = cA + sn*cB + C*cC ;  L_j.w = a*cB.w + cA.w  (C = 1-cos)
    __shared__ __align__(16) float4 s_cst[NF * 9];            // 4.5 KB
    __shared__ __align__(16) float  s_slab[64 * BSTR];        // 17.4 KB (warp-private quarters)
    __shared__ float s_angF[NF * 64];                         // 8 KB
    __shared__ int   s_slot[NF];
    __shared__ int   s_mslot[NF];
    __shared__ float s_mm[NF], s_mo[NF];

    const int tid  = threadIdx.x;
    const int lane = tid & 31;
    const int wid  = tid >> 5;
    const int h    = lane & 1;          // 0: rows 0,1   1: rows 2,3
    const int btw  = lane >> 1;         // batch within warp (0..15)
    const int bloc = wid * 16 + btw;    // batch within block (0..63)
    const int b0   = blockIdx.x * 64;
    const int gbat = b0 + bloc;

    // ---- per-frame meta ----
    if (tid < NF) {
        const int f = tid;
        int slot = -1;
        for (int j = 0; j < NDOF; ++j) if (ctrl[j] == f) slot = j;
        s_slot[f] = slot;
        int ms = -1; float mm = 0.f, mo = 0.f;
        for (int m = 0; m < 2; ++m) {
            if (mdst[m] == f) {
                const int sf = msrc[m];
                for (int j = 0; j < NDOF; ++j) if (ctrl[j] == sf) ms = j;
                mm = mmult[m]; mo = moff[m];
            }
        }
        s_mslot[f] = ms; s_mm[f] = mm; s_mo[f] = mo;
    }

    // ---- per (frame,row) constants ----
    if (tid < NF * 3) {
        const int f  = tid / 3;
        const int rr = tid - f * 3;
        const float4 orow = *reinterpret_cast<const float4*>(origins + f * 16 + rr * 4);
        const float kx = axes[f * 3 + 0], ky = axes[f * 3 + 1], kz = axes[f * 3 + 2];
        const int   ty = types[f];
        const float vr = orow.x * kx + orow.y * ky + orow.z * kz;
        float bx = 0.f, by = 0.f, bz = 0.f, cx = 0.f, cy = 0.f, cz = 0.f, ve = 0.f;
        if (ty == 1) {
            bx = orow.y * kz - orow.z * ky;
            by = orow.z * kx - orow.x * kz;
            bz = orow.x * ky - orow.y * kx;
            cx = fmaf(vr, kx, -orow.x);
            cy = fmaf(vr, ky, -orow.y);
            cz = fmaf(vr, kz, -orow.z);
        } else if (ty == 2) {
            ve = vr;
        }
        s_cst[(f * 3 + rr) * 3 + 0] = make_float4(orow.x, orow.y, orow.z, orow.w);
        s_cst[(f * 3 + rr) * 3 + 1] = make_float4(bx, by, bz, ve);
        s_cst[(f * 3 + rr) * 3 + 2] = make_float4(cx, cy, cz, 0.f);
    }

    // ---- stage raw joint angles into slab region (aliased), coalesced ----
    float* s_raw = s_slab;                  // 64*29 = 1856 <= 64*68 ✓
    for (int i = tid; i < 64 * NDOF; i += BLK) {
        const int bb = i / NDOF;
        s_raw[i] = (b0 + bb < Bn) ? ja[(size_t)b0 * NDOF + i] : 0.f;
    }
    __syncthreads();

    // ---- resolve final per-(frame,batch) angles ----
    for (int i = tid; i < NF * 64; i += BLK) {
        const int f  = i >> 6;
        const int bb = i & 63;
        const int sl = s_slot[f];
        float a;
        if (sl >= 0) a = s_raw[bb * NDOF + sl];
        else {
            const int ms = s_mslot[f];
            a = (ms >= 0) ? fmaf(s_raw[bb * NDOF + ms], s_mm[f], s_mo[f]) : 0.f;
        }
        s_angF[i] = a;
    }
    __syncthreads();        // raw consumed; slab reusable

    // ---- main chain: pair-split rows, warp-autonomous, staged flush ----
    // This thread's two pose rows (rows 2h and 2h+1)
    float A[4] = {0.f, 0.f, 0.f, 0.f};
    float Bv[4] = {0.f, 0.f, 0.f, 0.f};
    A[2 * h]      = 1.f;     // row 2h identity
    Bv[2 * h + 1] = 1.f;     // row 2h+1 identity
    float QA[4], QB[4];      // saved rows at frame 10
    #pragma unroll
    for (int j = 0; j < 4; ++j) { QA[j] = 0.f; QB[j] = 0.f; }

    float* const wslab = s_slab + wid * (16 * BSTR);
    float4* const out4 = reinterpret_cast<float4*>(out);
    const bool ok = (gbat < Bn);

    #pragma unroll
    for (int c = 0; c < NF / 4; ++c) {
        #pragma unroll
        for (int ff = 0; ff < 4; ++ff) {
            const int f = c * 4 + ff;
            if (f >= 30) {
                #pragma unroll
                for (int j = 0; j < 4; ++j) { A[j] = QA[j]; Bv[j] = QB[j]; }
            }
            const float a = s_angF[f * 64 + bloc];
            float sn, cs;
            fast_sincos(a, sn, cs);
            const float C = 1.f - cs;

            const float4* cf = s_cst + f * 9;
            float L[12];
            #pragma unroll
            for (int j = 0; j < 3; ++j) {
                const float4 cA = cf[j * 3 + 0];
                const float4 cB = cf[j * 3 + 1];
                const float4 cC = cf[j * 3 + 2];
                L[j * 4 + 0] = fmaf(C, cC.x, fmaf(sn, cB.x, cA.x));
                L[j * 4 + 1] = fmaf(C, cC.y, fmaf(sn, cB.y, cA.y));
                L[j * 4 + 2] = fmaf(C, cC.z, fmaf(sn, cB.z, cA.z));
                L[j * 4 + 3] = fmaf(a, cB.w, cA.w);
            }

            // row updates: r <- r @ L  (L row3 = 0001; works for row 3 too)
            {
                const float p0 = A[0], p1 = A[1], p2 = A[2], p3 = A[3];
                A[0] = fmaf(p0, L[0], fmaf(p1, L[4], p2 * L[8]));
                A[1] = fmaf(p0, L[1], fmaf(p1, L[5], p2 * L[9]));
                A[2] = fmaf(p0, L[2], fmaf(p1, L[6], p2 * L[10]));
                A[3] = fmaf(p0, L[3], fmaf(p1, L[7], fmaf(p2, L[11], p3)));
            }
            {
                const float p0 = Bv[0], p1 = Bv[1], p2 = Bv[2], p3 = Bv[3];
                Bv[0] = fmaf(p0, L[0], fmaf(p1, L[4], p2 * L[8]));
                Bv[1] = fmaf(p0, L[1], fmaf(p1, L[5], p2 * L[9]));
                Bv[2] = fmaf(p0, L[2], fmaf(p1, L[6], p2 * L[10]));
                Bv[3] = fmaf(p0, L[3], fmaf(p1, L[7], fmaf(p2, L[11], p3)));
            }
            if (f == 10) {
                #pragma unroll
                for (int j = 0; j < 4; ++j) { QA[j] = A[j]; QB[j] = Bv[j]; }
            }

            // stage rows 2h, 2h+1 of this frame
            float4* sp = reinterpret_cast<float4*>(wslab + btw * BSTR + (ff * 4 + h * 2) * 4);
            sp[0] = make_float4(A[0], A[1], A[2], A[3]);
            sp[1] = make_float4(Bv[0], Bv[1], Bv[2], Bv[3]);
        }

        __syncwarp();

        // flush: 16 batches x 256B; each iter = 2 batches x 256B contiguous
        #pragma unroll
        for (int it = 0; it < 8; ++it) {
            const int v = it * 32 + lane;
            const int b = v >> 4;               // warp-local batch
            const int w = v & 15;               // frame*4 + row within chunk
            const float4 val = *reinterpret_cast<const float4*>(wslab + b * BSTR + w * 4);
            const int gb = b0 + wid * 16 + b;
            if (gb < Bn)
                out4[(size_t)gb * (NF * 4) + c * 16 + w] = val;
        }

        __syncwarp();
    }
}

extern "C" void kernel_launch(void* const* d_in, const int* in_sizes, int n_in,
                              void* d_out, int out_size) {
    const float* ja      = (const float*)d_in[0];
    const float* axes    = (const float*)d_in[1];
    const float* origins = (const float*)d_in[2];
    const float* mm      = (const float*)d_in[3];
    const float* mo      = (const float*)d_in[4];
    const int*   ctrl    = (const int*)d_in[5];
    const int*   msrc    = (const int*)d_in[6];
    const int*   mdst    = (const int*)d_in[7];
    const int*   types   = (const int*)d_in[8];
    float*       out     = (float*)d_out;

    const int Bn   = in_sizes[0] / NDOF;
    const int grid = (Bn + 63) / 64;
    fk_kernel<<<grid, BLK>>>(ja, axes, origins, mm, mo, ctrl, msrc, mdst, types, out, Bn);
}

// round 9
// speedup vs baseline: 1.1665x; 1.1665x over previous
#include <cuda_runtime.h>

#define NF    32
#define NDOF  29
#define BLK   64            // 64 batches per block, 1 thread per batch, 2 warps
#define SSTR  52            // slab floats per batch (13 float4, conflict-free for .128)

__device__ __forceinline__ void fast_sincos(float a, float &s, float &c) {
    float q  = rintf(a * 0.63661977236758134f);
    int   iq = (int)q;
    float r  = fmaf(q, -1.5707962513e+0f, a);
    r        = fmaf(q, -7.5497894159e-8f, r);
    float r2 = r * r;
    float ps = fmaf(r2, -1.9841270e-4f, 8.3333333e-3f);
    ps       = fmaf(r2, ps, -1.6666667e-1f);
    float sr = fmaf(r * r2, ps, r);
    float pc = fmaf(r2, -1.3888889e-3f, 4.1666668e-2f);
    pc       = fmaf(r2, pc, -5.0e-1f);
    float cr = fmaf(r2, pc, 1.0f);
    bool  sw = (iq & 1);
    float ss = sw ? cr : sr;
    float cc = sw ? sr : cr;
    unsigned sgn_s = ((unsigned)(iq & 2)) << 30;
    unsigned sgn_c = ((unsigned)((iq + 1) & 2)) << 30;
    s = __uint_as_float(__float_as_uint(ss) ^ sgn_s);
    c = __uint_as_float(__float_as_uint(cc) ^ sgn_c);
}

__global__ void __launch_bounds__(BLK, 7)
fk_kernel(const float* __restrict__ ja,        // [B, 29]
          const float* __restrict__ axes,      // [32, 3]
          const float* __restrict__ origins,   // [32, 4, 4]
          const float* __restrict__ mmult,     // [2]
          const float* __restrict__ moff,      // [2]
          const int*   __restrict__ ctrl,      // [29]
          const int*   __restrict__ msrc,      // [2]
          const int*   __restrict__ mdst,      // [2]
          const int*   __restrict__ types,     // [32]
          float*       __restrict__ out,       // [B, 32, 4, 4]
          int Bn)
{
    // Per (frame, row j in 0..2) constants, 3 x float4:
    //   cA = (O_j.xyz, O_j.w)
    //   cB = (O_j x k [revolute], O_j.k [prismatic])
    //   cC = ((O_j.k)k - O_j.xyz [revolute], 0)
    // L_j.xyz = cA + sn*cB + C*cC ;  L_j.w = a*cB.w + cA.w  (C = 1-cos)
    __shared__ __align__(16) float4 s_cst[NF * 9];            // 4.5 KB
    __shared__ __align__(16) float  s_slab[BLK * SSTR];       // 13.3 KB (warp-private halves)
    __shared__ float s_angF[NF * BLK];                        // 8 KB
    __shared__ int   s_slot[NF];
    __shared__ int   s_mslot[NF];
    __shared__ float s_mm[NF], s_mo[NF];

    const int tid  = threadIdx.x;
    const int lane = tid & 31;
    const int wid  = tid >> 5;
    const int b0   = blockIdx.x * BLK;

    // ---- per-frame meta ----
    if (tid < NF) {
        const int f = tid;
        int slot = -1;
        for (int j = 0; j < NDOF; ++j) if (ctrl[j] == f) slot = j;
        s_slot[f] = slot;
        int ms = -1; float mm = 0.f, mo = 0.f;
        for (int m = 0; m < 2; ++m) {
            if (mdst[m] == f) {
                const int sf = msrc[m];
                for (int j = 0; j < NDOF; ++j) if (ctrl[j] == sf) ms = j;
                mm = mmult[m]; mo = moff[m];
            }
        }
        s_mslot[f] = ms; s_mm[f] = mm; s_mo[f] = mo;
    }

    // ---- per (frame,row) constants (96 entries, 64 threads) ----
    for (int i = tid; i < NF * 3; i += BLK) {
        const int f  = i / 3;
        const int rr = i - f * 3;
        const float4 orow = *reinterpret_cast<const float4*>(origins + f * 16 + rr * 4);
        const float kx = axes[f * 3 + 0], ky = axes[f * 3 + 1], kz = axes[f * 3 + 2];
        const int   ty = types[f];
        const float vr = orow.x * kx + orow.y * ky + orow.z * kz;
        float bx = 0.f, by = 0.f, bz = 0.f, cx = 0.f, cy = 0.f, cz = 0.f, ve = 0.f;
        if (ty == 1) {
            bx = orow.y * kz - orow.z * ky;
            by = orow.z * kx - orow.x * kz;
            bz = orow.x * ky - orow.y * kx;
            cx = fmaf(vr, kx, -orow.x);
            cy = fmaf(vr, ky, -orow.y);
            cz = fmaf(vr, kz, -orow.z);
        } else if (ty == 2) {
            ve = vr;
        }
        s_cst[(f * 3 + rr) * 3 + 0] = make_float4(orow.x, orow.y, orow.z, orow.w);
        s_cst[(f * 3 + rr) * 3 + 1] = make_float4(bx, by, bz, ve);
        s_cst[(f * 3 + rr) * 3 + 2] = make_float4(cx, cy, cz, 0.f);
    }

    // ---- stage raw joint angles into slab region (aliased), coalesced ----
    float* s_raw = s_slab;                  // 64*29 = 1856 <= 64*52 ✓
    for (int i = tid; i < BLK * NDOF; i += BLK) {
        const int bb = i / NDOF;
        s_raw[i] = (b0 + bb < Bn) ? ja[(size_t)b0 * NDOF + i] : 0.f;
    }
    __syncthreads();

    // ---- resolve final per-(frame,batch) angles ----
    for (int i = tid; i < NF * BLK; i += BLK) {
        const int f  = i >> 6;
        const int bb = i & 63;
        const int sl = s_slot[f];
        float a;
        if (sl >= 0) a = s_raw[bb * NDOF + sl];
        else {
            const int ms = s_mslot[f];
            a = (ms >= 0) ? fmaf(s_raw[bb * NDOF + ms], s_mm[f], s_mo[f]) : 0.f;
        }
        s_angF[i] = a;
    }
    __syncthreads();        // raw consumed; slab reusable

    // ---- main chain: phase-split chunks, warp-autonomous, coalesced flush ----
    float P[12];
    #pragma unroll
    for (int j = 0; j < 12; ++j) P[j] = 0.f;
    P[0] = 1.f; P[5] = 1.f; P[10] = 1.f;
    float Q[12];
    #pragma unroll
    for (int j = 0; j < 12; ++j) Q[j] = 0.f;

    float* const wslab = s_slab + wid * (32 * SSTR);
    float4* const out4 = reinterpret_cast<float4*>(out);

    #pragma unroll
    for (int c = 0; c < NF / 4; ++c) {
        // -- phase A: build 4 independent local transforms (ILP) --
        float L[4][12];
        #pragma unroll
        for (int ff = 0; ff < 4; ++ff) {
            const int f = c * 4 + ff;
            const float a = s_angF[f * BLK + tid];
            float sn, cs;
            fast_sincos(a, sn, cs);
            const float C = 1.f - cs;
            const float4* cf = s_cst + f * 9;
            #pragma unroll
            for (int j = 0; j < 3; ++j) {
                const float4 cA = cf[j * 3 + 0];
                const float4 cB = cf[j * 3 + 1];
                const float4 cC = cf[j * 3 + 2];
                L[ff][j * 4 + 0] = fmaf(C, cC.x, fmaf(sn, cB.x, cA.x));
                L[ff][j * 4 + 1] = fmaf(C, cC.y, fmaf(sn, cB.y, cA.y));
                L[ff][j * 4 + 2] = fmaf(C, cC.z, fmaf(sn, cB.z, cA.z));
                L[ff][j * 4 + 3] = fmaf(a, cB.w, cA.w);
            }
        }

        // -- phase B: serial chain updates + stage --
        #pragma unroll
        for (int ff = 0; ff < 4; ++ff) {
            const int f = c * 4 + ff;
            if (f >= 30) {
                #pragma unroll
                for (int j = 0; j < 12; ++j) P[j] = Q[j];
            }
            #pragma unroll
            for (int rr = 0; rr < 3; ++rr) {
                const float p0 = P[rr * 4 + 0], p1 = P[rr * 4 + 1];
                const float p2 = P[rr * 4 + 2], p3 = P[rr * 4 + 3];
                P[rr * 4 + 0] = fmaf(p0, L[ff][0], fmaf(p1, L[ff][4], p2 * L[ff][8]));
                P[rr * 4 + 1] = fmaf(p0, L[ff][1], fmaf(p1, L[ff][5], p2 * L[ff][9]));
                P[rr * 4 + 2] = fmaf(p0, L[ff][2], fmaf(p1, L[ff][6], p2 * L[ff][10]));
                P[rr * 4 + 3] = fmaf(p0, L[ff][3], fmaf(p1, L[ff][7], fmaf(p2, L[ff][11], p3)));
            }
            if (f == 10) {
                #pragma unroll
                for (int j = 0; j < 12; ++j) Q[j] = P[j];
            }
            float4* sp = reinterpret_cast<float4*>(wslab + lane * SSTR + ff * 12);
            sp[0] = make_float4(P[0], P[1], P[2],  P[3]);
            sp[1] = make_float4(P[4], P[5], P[6],  P[7]);
            sp[2] = make_float4(P[8], P[9], P[10], P[11]);
        }

        __syncwarp();

        // -- flush: each iter writes 2 batches x 256 B contiguous --
        #pragma unroll
        for (int it = 0; it < 16; ++it) {
            const int b = it * 2 + (lane >> 4);    // warp-local batch
            const int w = lane & 15;               // frame*4 + row within chunk
            const int fi = w >> 2;
            const int rr = w & 3;
            float4 val;
            if (rr < 3) val = *reinterpret_cast<const float4*>(wslab + b * SSTR + fi * 12 + rr * 4);
            else        val = make_float4(0.f, 0.f, 0.f, 1.f);
            const int gbat = b0 + (wid << 5) + b;
            if (gbat < Bn)
                out4[(size_t)gbat * (NF * 4) + c * 16 + w] = val;
        }

        __syncwarp();
    }
}

extern "C" void kernel_launch(void* const* d_in, const int* in_sizes, int n_in,
                              void* d_out, int out_size) {
    const float* ja      = (const float*)d_in[0];
    const float* axes    = (const float*)d_in[1];
    const float* origins = (const float*)d_in[2];
    const float* mm      = (const float*)d_in[3];
    const float* mo      = (const float*)d_in[4];
    const int*   ctrl    = (const int*)d_in[5];
    const int*   msrc    = (const int*)d_in[6];
    const int*   mdst    = (const int*)d_in[7];
    const int*   types   = (const int*)d_in[8];
    float*       out     = (float*)d_out;

    const int Bn   = in_sizes[0] / NDOF;
    const int grid = (Bn + BLK - 1) / BLK;
    fk_kernel<<<grid, BLK>>>(ja, axes, origins, mm, mo, ctrl, msrc, mdst, types, out, Bn);
}

// round 10
// speedup vs baseline: 1.2474x; 1.0693x over previous
#include <cuda_runtime.h>

#define NF    32
#define NDOF  29
#define BLK   64            // 64 batches per block, 1 thread per batch, 2 warps
#define CH    2             // frames per chunk
#define TS    28            // slab floats per batch: 2 frames * 12 + 4 pad

__device__ __forceinline__ void fast_sincos(float a, float &s, float &c) {
    float q  = rintf(a * 0.63661977236758134f);
    int   iq = (int)q;
    float r  = fmaf(q, -1.5707962513e+0f, a);
    r        = fmaf(q, -7.5497894159e-8f, r);
    float r2 = r * r;
    float ps = fmaf(r2, -1.9841270e-4f, 8.3333333e-3f);
    ps       = fmaf(r2, ps, -1.6666667e-1f);
    float sr = fmaf(r * r2, ps, r);
    float pc = fmaf(r2, -1.3888889e-3f, 4.1666668e-2f);
    pc       = fmaf(r2, pc, -5.0e-1f);
    float cr = fmaf(r2, pc, 1.0f);
    bool  sw = (iq & 1);
    float ss = sw ? cr : sr;
    float cc = sw ? sr : cr;
    unsigned sgn_s = ((unsigned)(iq & 2)) << 30;
    unsigned sgn_c = ((unsigned)((iq + 1) & 2)) << 30;
    s = __uint_as_float(__float_as_uint(ss) ^ sgn_s);
    c = __uint_as_float(__float_as_uint(cc) ^ sgn_c);
}

__global__ void __launch_bounds__(BLK, 7)
fk_kernel(const float* __restrict__ ja,        // [B, 29]
          const float* __restrict__ axes,      // [32, 3]
          const float* __restrict__ origins,   // [32, 4, 4]
          const float* __restrict__ mmult,     // [2]
          const float* __restrict__ moff,      // [2]
          const int*   __restrict__ ctrl,      // [29]
          const int*   __restrict__ msrc,      // [2]
          const int*   __restrict__ mdst,      // [2]
          const int*   __restrict__ types,     // [32]
          float*       __restrict__ out,       // [B, 32, 4, 4]
          int Bn)
{
    // Per (frame, row j in 0..2) constants, 3 x float4:
    //   cA = (O_j.xyz, O_j.w)
    //   cB = (O_j x k [revolute], O_j.k [prismatic])
    //   cC = ((O_j.k)k - O_j.xyz [revolute], 0)
    // L_j.xyz = cA + sn*cB + C*cC ;  L_j.w = a*cB.w + cA.w  (C = 1-cos)
    __shared__ __align__(16) float4 s_cst[NF * 9];            // 4.5 KB
    __shared__ __align__(16) float  s_slab[BLK * TS];         // 7 KB (warp-private halves)
    __shared__ float s_angF[NF * BLK];                        // 8 KB
    __shared__ int   s_slot[NF];
    __shared__ int   s_mslot[NF];
    __shared__ float s_mm[NF], s_mo[NF];

    const int tid  = threadIdx.x;
    const int lane = tid & 31;
    const int wid  = tid >> 5;
    const int b0   = blockIdx.x * BLK;

    // ---- per-frame meta ----
    if (tid < NF) {
        const int f = tid;
        int slot = -1;
        for (int j = 0; j < NDOF; ++j) if (ctrl[j] == f) slot = j;
        s_slot[f] = slot;
        int ms = -1; float mm = 0.f, mo = 0.f;
        for (int m = 0; m < 2; ++m) {
            if (mdst[m] == f) {
                const int sf = msrc[m];
                for (int j = 0; j < NDOF; ++j) if (ctrl[j] == sf) ms = j;
                mm = mmult[m]; mo = moff[m];
            }
        }
        s_mslot[f] = ms; s_mm[f] = mm; s_mo[f] = mo;
    }

    // ---- per (frame,row) constants ----
    for (int i = tid; i < NF * 3; i += BLK) {
        const int f  = i / 3;
        const int rr = i - f * 3;
        const float4 orow = *reinterpret_cast<const float4*>(origins + f * 16 + rr * 4);
        const float kx = axes[f * 3 + 0], ky = axes[f * 3 + 1], kz = axes[f * 3 + 2];
        const int   ty = types[f];
        const float vr = orow.x * kx + orow.y * ky + orow.z * kz;
        float bx = 0.f, by = 0.f, bz = 0.f, cx = 0.f, cy = 0.f, cz = 0.f, ve = 0.f;
        if (ty == 1) {
            bx = orow.y * kz - orow.z * ky;
            by = orow.z * kx - orow.x * kz;
            bz = orow.x * ky - orow.y * kx;
            cx = fmaf(vr, kx, -orow.x);
            cy = fmaf(vr, ky, -orow.y);
            cz = fmaf(vr, kz, -orow.z);
        } else if (ty == 2) {
            ve = vr;
        }
        s_cst[(f * 3 + rr) * 3 + 0] = make_float4(orow.x, orow.y, orow.z, orow.w);
        s_cst[(f * 3 + rr) * 3 + 1] = make_float4(bx, by, bz, ve);
        s_cst[(f * 3 + rr) * 3 + 2] = make_float4(cx, cy, cz, 0.f);
    }

    // ---- stage raw joint angles into s_angF region (aliased), coalesced ----
    float* s_raw = s_angF;                  // 64*29 = 1856 <= 2048 ✓
    for (int i = tid; i < BLK * NDOF; i += BLK) {
        const int bb = i / NDOF;
        s_raw[i] = (b0 + bb < Bn) ? ja[(size_t)b0 * NDOF + i] : 0.f;
    }
    __syncthreads();

    // ---- resolve final per-(frame,batch) angles into registers then smem ----
    // (must read all raw first since s_angF aliases s_raw)
    {
        float av[NF];
        const float* raw = s_raw + tid * NDOF;
        #pragma unroll
        for (int f = 0; f < NF; ++f) {
            const int sl = s_slot[f];
            float a;
            if (sl >= 0) a = raw[sl];
            else {
                const int ms = s_mslot[f];
                a = (ms >= 0) ? fmaf(raw[ms], s_mm[f], s_mo[f]) : 0.f;
            }
            av[f] = a;
        }
        __syncthreads();
        #pragma unroll
        for (int f = 0; f < NF; ++f) s_angF[f * BLK + tid] = av[f];
    }
    __syncthreads();

    // ---- main chain: 2-frame phase-split chunks, warp-autonomous flush ----
    float P[12];
    #pragma unroll
    for (int j = 0; j < 12; ++j) P[j] = 0.f;
    P[0] = 1.f; P[5] = 1.f; P[10] = 1.f;
    float Q[12];
    #pragma unroll
    for (int j = 0; j < 12; ++j) Q[j] = 0.f;

    float* const wslab = s_slab + wid * (32 * TS);
    float4* const out4 = reinterpret_cast<float4*>(out);

    #pragma unroll
    for (int c = 0; c < NF / CH; ++c) {
        // -- phase A: build CH independent local transforms --
        float L[CH][12];
        #pragma unroll
        for (int ff = 0; ff < CH; ++ff) {
            const int f = c * CH + ff;
            const float a = s_angF[f * BLK + tid];
            float sn, cs;
            fast_sincos(a, sn, cs);
            const float C = 1.f - cs;
            const float4* cf = s_cst + f * 9;
            #pragma unroll
            for (int j = 0; j < 3; ++j) {
                const float4 cA = cf[j * 3 + 0];
                const float4 cB = cf[j * 3 + 1];
                const float4 cC = cf[j * 3 + 2];
                L[ff][j * 4 + 0] = fmaf(C, cC.x, fmaf(sn, cB.x, cA.x));
                L[ff][j * 4 + 1] = fmaf(C, cC.y, fmaf(sn, cB.y, cA.y));
                L[ff][j * 4 + 2] = fmaf(C, cC.z, fmaf(sn, cB.z, cA.z));
                L[ff][j * 4 + 3] = fmaf(a, cB.w, cA.w);
            }
        }

        // -- phase B: serial chain updates + stage --
        #pragma unroll
        for (int ff = 0; ff < CH; ++ff) {
            const int f = c * CH + ff;
            if (f >= 30) {
                #pragma unroll
                for (int j = 0; j < 12; ++j) P[j] = Q[j];
            }
            #pragma unroll
            for (int rr = 0; rr < 3; ++rr) {
                const float p0 = P[rr * 4 + 0], p1 = P[rr * 4 + 1];
                const float p2 = P[rr * 4 + 2], p3 = P[rr * 4 + 3];
                P[rr * 4 + 0] = fmaf(p0, L[ff][0], fmaf(p1, L[ff][4], p2 * L[ff][8]));
                P[rr * 4 + 1] = fmaf(p0, L[ff][1], fmaf(p1, L[ff][5], p2 * L[ff][9]));
                P[rr * 4 + 2] = fmaf(p0, L[ff][2], fmaf(p1, L[ff][6], p2 * L[ff][10]));
                P[rr * 4 + 3] = fmaf(p0, L[ff][3], fmaf(p1, L[ff][7], fmaf(p2, L[ff][11], p3)));
            }
            if (f == 10) {
                #pragma unroll
                for (int j = 0; j < 12; ++j) Q[j] = P[j];
            }
            float4* sp = reinterpret_cast<float4*>(wslab + lane * TS + ff * 12);
            sp[0] = make_float4(P[0], P[1], P[2],  P[3]);
            sp[1] = make_float4(P[4], P[5], P[6],  P[7]);
            sp[2] = make_float4(P[8], P[9], P[10], P[11]);
        }

        __syncwarp();

        // -- flush: each iter = 4 batches x 128 B contiguous (fully coalesced) --
        #pragma unroll
        for (int it = 0; it < 8; ++it) {
            const int v = it * 32 + lane;
            const int b = v >> 3;               // warp-local batch (0..31)
            const int w = v & 7;                // frame*4 + row within chunk
            const int fi = w >> 2;
            const int rr = w & 3;
            float4 val;
            if (rr < 3) val = *reinterpret_cast<const float4*>(wslab + b * TS + fi * 12 + rr * 4);
            else        val = make_float4(0.f, 0.f, 0.f, 1.f);
            const int gbat = b0 + (wid << 5) + b;
            if (gbat < Bn)
                out4[(size_t)gbat * (NF * 4) + c * (CH * 4) + w] = val;
        }

        __syncwarp();
    }
}

extern "C" void kernel_launch(void* const* d_in, const int* in_sizes, int n_in,
                              void* d_out, int out_size) {
    const float* ja      = (const float*)d_in[0];
    const float* axes    = (const float*)d_in[1];
    const float* origins = (const float*)d_in[2];
    const float* mm      = (const float*)d_in[3];
    const float* mo      = (const float*)d_in[4];
    const int*   ctrl    = (const int*)d_in[5];
    const int*   msrc    = (const int*)d_in[6];
    const int*   mdst    = (const int*)d_in[7];
    const int*   types   = (const int*)d_in[8];
    float*       out     = (float*)d_out;

    const int Bn   = in_sizes[0] / NDOF;
    const int grid = (Bn + BLK - 1) / BLK;
    fk_kernel<<<grid, BLK>>>(ja, axes, origins, mm, mo, ctrl, msrc, mdst, types, out, Bn);
}